// round 1
// baseline (speedup 1.0000x reference)
#include <cuda_runtime.h>

// ContinuousPositionBias for GB300.
// Inputs (metadata order):
//   0: glob_pos      (1,32,4) f32
//   1: coords_table  (2209,2) f32
//   2: rpi           (576,576) i32   -- UNUSED (computed analytically)
//   3: W1            (2,512) f32
//   4: b1            (512,)  f32
//   5: W2            (512,16) f32
//   6: num_prefix_tokens (scalar, =1, hardcoded)
// Output: (32,16,577,577) f32

#define NT     2209      // 47*47 relative-position table entries
#define NTOK   576       // 24*24 tokens
#define HEADS  16
#define DHID   512
#define BATCH  32
#define OW     577       // NTOK + num_prefix_tokens
#define PLANE  (OW*OW)   // 332929

// scratch: bias in (b, h, t) layout -> coalesced writes and coalesced plane stage
__device__ float g_bias[BATCH * HEADS * NT];

typedef unsigned long long u64;

__device__ __forceinline__ u64 fma2(u64 a, u64 b, u64 c) {
    u64 d;
    asm("fma.rn.f32x2 %0, %1, %2, %3;" : "=l"(d) : "l"(a), "l"(b), "l"(c));
    return d;
}
__device__ __forceinline__ u64 pack2(float x) {
    u64 d;
    asm("mov.b64 %0, {%1, %1};" : "=l"(d) : "f"(x));
    return d;
}
__device__ __forceinline__ void unpack2(u64 v, float& lo, float& hi) {
    asm("mov.b64 {%0, %1}, %2;" : "=f"(lo), "=f"(hi) : "l"(v));
}

// ---------------------------------------------------------------------------
// Kernel A: bias[b,h,t] = relu((ctab[t]+pos[b]) @ W1 + b1) @ W2
// One thread per t, 16 head-accumulators packed as 8 f32x2.
// ---------------------------------------------------------------------------
__global__ __launch_bounds__(128) void mlp_kernel(
    const float* __restrict__ glob, const float* __restrict__ ctab,
    const float* __restrict__ W1,   const float* __restrict__ b1,
    const float* __restrict__ W2)
{
    __shared__ __align__(16) float4 w1s[DHID];          // (W1[0][d], W1[1][d], b1[d], 0)
    __shared__ __align__(16) float  w2s[DHID * HEADS];  // same layout as W2

    const int tid = threadIdx.x;

    // stage W2 (512x16 f32 = 32KB) and fused W1/b1 (8KB)
    {
        const float4* src = (const float4*)W2;
        float4* dst = (float4*)w2s;
        #pragma unroll
        for (int k = tid; k < DHID * HEADS / 4; k += 128) dst[k] = src[k];
        for (int d = tid; d < DHID; d += 128)
            w1s[d] = make_float4(W1[d], W1[DHID + d], b1[d], 0.0f);
    }
    __syncthreads();

    const int b = blockIdx.y;
    // per-batch position offset (cheap, recomputed per thread)
    const float g0 = glob[b*4+0], g1 = glob[b*4+1];
    const float g2 = glob[b*4+2], g3 = glob[b*4+3];
    float p0 = g2 / g0 * 8.0f;
    float p1 = g3 / g1 * 8.0f;
    p0 = copysignf(log2f(fabsf(p0) + 1.0f), p0) * (2.0f / 3.0f) - 1.0f;
    p1 = copysignf(log2f(fabsf(p1) + 1.0f), p1) * (2.0f / 3.0f) - 1.0f;

    const int t = blockIdx.x * 128 + tid;
    if (t >= NT) return;

    const float c0 = ctab[2*t]     + p0;
    const float c1 = ctab[2*t + 1] + p1;

    u64 acc[8];
    #pragma unroll
    for (int k = 0; k < 8; k++) acc[k] = 0ull;

    const ulonglong2* __restrict__ w2q = (const ulonglong2*)w2s;  // 4 x LDS.128 per d

    #pragma unroll 4
    for (int d = 0; d < DHID; d++) {
        const float4 w = w1s[d];
        float hd = fmaf(c0, w.x, fmaf(c1, w.y, w.z));
        hd = fmaxf(hd, 0.0f);
        const u64 hd2 = pack2(hd);
        const ulonglong2 q0 = w2q[d*4 + 0];
        const ulonglong2 q1 = w2q[d*4 + 1];
        const ulonglong2 q2 = w2q[d*4 + 2];
        const ulonglong2 q3 = w2q[d*4 + 3];
        acc[0] = fma2(hd2, q0.x, acc[0]);
        acc[1] = fma2(hd2, q0.y, acc[1]);
        acc[2] = fma2(hd2, q1.x, acc[2]);
        acc[3] = fma2(hd2, q1.y, acc[3]);
        acc[4] = fma2(hd2, q2.x, acc[4]);
        acc[5] = fma2(hd2, q2.y, acc[5]);
        acc[6] = fma2(hd2, q3.x, acc[6]);
        acc[7] = fma2(hd2, q3.y, acc[7]);
    }

    float* outb = g_bias + (size_t)b * (HEADS * NT) + t;
    #pragma unroll
    for (int k = 0; k < 8; k++) {
        float lo, hi;
        unpack2(acc[k], lo, hi);
        outb[(2*k)     * NT] = lo;   // head 2k   : consecutive t across warp -> coalesced
        outb[(2*k + 1) * NT] = hi;   // head 2k+1
    }
}

// ---------------------------------------------------------------------------
// Kernel B: out[b,h,r,c] = (r>0 && c>0) ? bias[b,h, Bi(r-1) - Bj(c-1) + 1104] : 0
// One block per (plane, 58-row chunk). Bias plane staged in SMEM (8.8KB);
// rpi computed analytically (zero global reads for indices).
// ---------------------------------------------------------------------------
#define ROWS_PER_BLK 58   // ceil(577/58) = 10 chunks

__global__ __launch_bounds__(256) void scatter_kernel(float* __restrict__ out)
{
    __shared__ float sh[NT];
    __shared__ int   shBi[NTOK];

    const int tid   = threadIdx.x;
    const int plane = blockIdx.y;                    // b*16 + h

    const float* __restrict__ bp = g_bias + (size_t)plane * NT;
    for (int k = tid; k < NT; k += 256) sh[k] = bp[k];
    for (int i = tid; i < NTOK; i += 256) shBi[i] = (i / 24) * 47 + (i % 24);
    __syncthreads();

    const int r0 = blockIdx.x * ROWS_PER_BLK;
    const int r1 = min(r0 + ROWS_PER_BLK, OW);
    float* __restrict__ pb = out + (size_t)plane * PLANE;

    for (int c = tid; c < OW; c += 256) {
        const bool cz = (c == 0);
        const int  j  = cz ? 0 : (c - 1);
        const int  tb = 1104 - ((j / 24) * 47 + (j % 24));  // rpi = Bi - Bj + 1104
        float* op = pb + (size_t)r0 * OW + c;
        for (int r = r0; r < r1; ++r) {
            float v = 0.0f;
            if (r > 0 && !cz) v = sh[shBi[r - 1] + tb];
            *op = v;                                  // 128B coalesced per warp
            op += OW;
        }
    }
}

// ---------------------------------------------------------------------------
extern "C" void kernel_launch(void* const* d_in, const int* in_sizes, int n_in,
                              void* d_out, int out_size)
{
    const float* glob = (const float*)d_in[0];
    const float* ctab = (const float*)d_in[1];
    /* d_in[2] = rpi (unused, computed analytically) */
    const float* W1   = (const float*)d_in[3];
    const float* b1   = (const float*)d_in[4];
    const float* W2   = (const float*)d_in[5];
    float* out        = (float*)d_out;

    mlp_kernel<<<dim3((NT + 127) / 128, BATCH), 128>>>(glob, ctab, W1, b1, W2);
    scatter_kernel<<<dim3((OW + ROWS_PER_BLK - 1) / ROWS_PER_BLK, BATCH * HEADS), 256>>>(out);
}

// round 2
// speedup vs baseline: 1.0828x; 1.0828x over previous
#include <cuda_runtime.h>

// ContinuousPositionBias for GB300 — round 2.
// Inputs (metadata order):
//   0: glob_pos (1,32,4) f32 | 1: coords_table (2209,2) f32 | 2: rpi (unused)
//   3: W1 (2,512) f32 | 4: b1 (512,) f32 | 5: W2 (512,16) f32 | 6: num_prefix_tokens (=1)
// Output: (32,16,577,577) f32

#define NT     2209      // 47*47
#define HEADS  16
#define DHID   512
#define BATCH  32
#define OW     577
#define PLANE  (OW*OW)   // 332929 (odd!)

__device__ float g_bias[BATCH * HEADS * NT];   // (b,h,t) layout

typedef unsigned long long u64;

__device__ __forceinline__ u64 fma2(u64 a, u64 b, u64 c) {
    u64 d;
    asm("fma.rn.f32x2 %0, %1, %2, %3;" : "=l"(d) : "l"(a), "l"(b), "l"(c));
    return d;
}
__device__ __forceinline__ u64 pack2(float x) {
    u64 d;
    asm("mov.b64 %0, {%1, %1};" : "=l"(d) : "f"(x));
    return d;
}
__device__ __forceinline__ void unpack2(u64 v, float& lo, float& hi) {
    asm("mov.b64 {%0, %1}, %2;" : "=f"(lo), "=f"(hi) : "l"(v));
}

// ---------------------------------------------------------------------------
// Kernel A: bias[b,h,t] = relu((ctab[t]+pos[b]) @ W1 + b1) @ W2
// 128 threads/block, 2 t-values per thread (amortize uniform LDS broadcasts).
// ---------------------------------------------------------------------------
__global__ __launch_bounds__(128) void mlp_kernel(
    const float* __restrict__ glob, const float* __restrict__ ctab,
    const float* __restrict__ W1,   const float* __restrict__ b1,
    const float* __restrict__ W2)
{
    __shared__ __align__(16) float4 w1s[DHID];          // (W1[0][d], W1[1][d], b1[d], 0)
    __shared__ __align__(16) float  w2s[DHID * HEADS];

    const int tid = threadIdx.x;
    {
        const float4* src = (const float4*)W2;
        float4* dst = (float4*)w2s;
        #pragma unroll
        for (int k = tid; k < DHID * HEADS / 4; k += 128) dst[k] = src[k];
        for (int d = tid; d < DHID; d += 128)
            w1s[d] = make_float4(W1[d], W1[DHID + d], b1[d], 0.0f);
    }
    __syncthreads();

    const int b = blockIdx.y;
    const float g0 = glob[b*4+0], g1 = glob[b*4+1];
    const float g2 = glob[b*4+2], g3 = glob[b*4+3];
    float p0 = g2 / g0 * 8.0f;
    float p1 = g3 / g1 * 8.0f;
    p0 = copysignf(log2f(fabsf(p0) + 1.0f), p0) * (2.0f / 3.0f) - 1.0f;
    p1 = copysignf(log2f(fabsf(p1) + 1.0f), p1) * (2.0f / 3.0f) - 1.0f;

    const int t0 = blockIdx.x * 256 + tid;
    const int t1 = t0 + 128;
    const bool v0 = (t0 < NT), v1 = (t1 < NT);

    float a0 = 0.f, a1 = 0.f, c0 = 0.f, c1 = 0.f;
    if (v0) { a0 = ctab[2*t0] + p0; a1 = ctab[2*t0+1] + p1; }
    if (v1) { c0 = ctab[2*t1] + p0; c1 = ctab[2*t1+1] + p1; }

    u64 accA[8], accB[8];
    #pragma unroll
    for (int k = 0; k < 8; k++) { accA[k] = 0ull; accB[k] = 0ull; }

    const ulonglong2* __restrict__ w2q = (const ulonglong2*)w2s;

    #pragma unroll 2
    for (int d = 0; d < DHID; d++) {
        const float4 w = w1s[d];
        float hA = fmaxf(fmaf(a0, w.x, fmaf(a1, w.y, w.z)), 0.0f);
        float hB = fmaxf(fmaf(c0, w.x, fmaf(c1, w.y, w.z)), 0.0f);
        const u64 hA2 = pack2(hA);
        const u64 hB2 = pack2(hB);
        const ulonglong2 q0 = w2q[d*4 + 0];
        const ulonglong2 q1 = w2q[d*4 + 1];
        const ulonglong2 q2 = w2q[d*4 + 2];
        const ulonglong2 q3 = w2q[d*4 + 3];
        accA[0] = fma2(hA2, q0.x, accA[0]);  accB[0] = fma2(hB2, q0.x, accB[0]);
        accA[1] = fma2(hA2, q0.y, accA[1]);  accB[1] = fma2(hB2, q0.y, accB[1]);
        accA[2] = fma2(hA2, q1.x, accA[2]);  accB[2] = fma2(hB2, q1.x, accB[2]);
        accA[3] = fma2(hA2, q1.y, accA[3]);  accB[3] = fma2(hB2, q1.y, accB[3]);
        accA[4] = fma2(hA2, q2.x, accA[4]);  accB[4] = fma2(hB2, q2.x, accB[4]);
        accA[5] = fma2(hA2, q2.y, accA[5]);  accB[5] = fma2(hB2, q2.y, accB[5]);
        accA[6] = fma2(hA2, q3.x, accA[6]);  accB[6] = fma2(hB2, q3.x, accB[6]);
        accA[7] = fma2(hA2, q3.y, accA[7]);  accB[7] = fma2(hB2, q3.y, accB[7]);
    }

    float* base = g_bias + (size_t)b * (HEADS * NT);
    if (v0) {
        #pragma unroll
        for (int k = 0; k < 8; k++) {
            float lo, hi; unpack2(accA[k], lo, hi);
            base[(2*k)   * NT + t0] = lo;
            base[(2*k+1) * NT + t0] = hi;
        }
    }
    if (v1) {
        #pragma unroll
        for (int k = 0; k < 8; k++) {
            float lo, hi; unpack2(accB[k], lo, hi);
            base[(2*k)   * NT + t1] = lo;
            base[(2*k+1) * NT + t1] = hi;
        }
    }
}

// ---------------------------------------------------------------------------
// Kernel B: out[b,h,r,c]. Block = (ib, plane): 24-row band r=1+24*ib+ii.
// Band needs only bias[47*ib .. 47*ib+1128). Staged PADDED (k + k/4) so the
// lane-stride(-4) gather becomes physical stride -5 -> conflict-free.
//   widx = ii + 1104 - Bj(j),  Bj(j) = j + 23*(j/24)
// Stores: float4 STG.128 body + <=3 head/tail scalars per row (alignment
// shifts because PLANE is odd).
// ---------------------------------------------------------------------------
#define STAGE_N 1128   // 24*47
#define WPAD    1410   // 1128 + 1128/4

__global__ __launch_bounds__(256) void scatter_kernel(float* __restrict__ out)
{
    __shared__ float wpad[WPAD];
    const int tid   = threadIdx.x;
    const int ib    = blockIdx.x;    // 0..23
    const int plane = blockIdx.y;    // 0..511

    const float* __restrict__ bp = g_bias + (size_t)plane * NT + 47 * ib;
    for (int k = tid; k < STAGE_N; k += 256)
        wpad[k + (k >> 2)] = bp[k];
    __syncthreads();

    const int w    = tid >> 5;
    const int lane = tid & 31;
    float* __restrict__ pb = out + (size_t)plane * PLANE;

    for (int rr = 0; rr < 4; rr++) {
        bool zero_row = false;
        int r;
        if (rr < 3) {
            r = 1 + 24 * ib + (w + 8 * rr);
        } else {
            if (!(ib == 0 && w == 7)) break;   // one warp fills row 0 with zeros
            r = 0; zero_row = true;
        }
        const int A = zero_row ? 0 : ((r - 1 - 24 * ib) + 1104);  // ii + 1104
        const size_t gb = (size_t)r * OW;
        const int a  = (int)(((size_t)plane * PLANE + gb) & 3);
        const int s  = (4 - a) & 3;
        const int nb = (OW - s) >> 2;

        // vector body
        for (int q = lane; q < nb; q += 32) {
            const int cbase = s + 4 * q;
            float4 v;
            float* vv = (float*)&v;
            #pragma unroll
            for (int e = 0; e < 4; e++) {
                const int c = cbase + e;
                float val = 0.0f;
                if (!zero_row && c >= 1) {
                    const int j    = c - 1;
                    const int jb   = (j * 2731) >> 16;      // j / 24
                    const int widx = A - j - 23 * jb;       // ii + 1104 - Bj(j)
                    val = wpad[widx + (widx >> 2)];
                }
                vv[e] = val;
            }
            *(float4*)(pb + gb + cbase) = v;
        }

        // head (lanes 0..2) and tail (lanes 3..5) scalars
        const int tc = s + 4 * nb;
        int c = -1;
        if (lane < 3)      { if (lane < s) c = lane; }
        else if (lane < 6) { int cc = tc + (lane - 3); if (cc < OW) c = cc; }
        if (c >= 0) {
            float val = 0.0f;
            if (!zero_row && c >= 1) {
                const int j    = c - 1;
                const int jb   = (j * 2731) >> 16;
                const int widx = A - j - 23 * jb;
                val = wpad[widx + (widx >> 2)];
            }
            pb[gb + c] = val;
        }
    }
}

// ---------------------------------------------------------------------------
extern "C" void kernel_launch(void* const* d_in, const int* in_sizes, int n_in,
                              void* d_out, int out_size)
{
    const float* glob = (const float*)d_in[0];
    const float* ctab = (const float*)d_in[1];
    const float* W1   = (const float*)d_in[3];
    const float* b1   = (const float*)d_in[4];
    const float* W2   = (const float*)d_in[5];
    float* out        = (float*)d_out;

    mlp_kernel<<<dim3((NT + 255) / 256, BATCH), 128>>>(glob, ctab, W1, b1, W2);
    scatter_kernel<<<dim3(24, BATCH * HEADS), 256>>>(out);
}

// round 3
// speedup vs baseline: 1.4961x; 1.3816x over previous
#include <cuda_runtime.h>

// ContinuousPositionBias for GB300 — round 3.
// Inputs: 0 glob_pos(1,32,4) f32 | 1 coords_table(2209,2) f32 | 2 rpi(unused)
//         3 W1(2,512) | 4 b1(512) | 5 W2(512,16) | 6 num_prefix_tokens(=1)
// Output: (32,16,577,577) f32

#define NT     2209
#define HEADS  16
#define DHID   512
#define BATCH  32
#define OW     577
#define PLANE  (OW*OW)    // 332929

__device__ float g_bias[BATCH * HEADS * NT];   // (b,h,t)

typedef unsigned long long u64;

__device__ __forceinline__ u64 fma2(u64 a, u64 b, u64 c) {
    u64 d;
    asm("fma.rn.f32x2 %0, %1, %2, %3;" : "=l"(d) : "l"(a), "l"(b), "l"(c));
    return d;
}
__device__ __forceinline__ u64 pack2(float x) {
    u64 d;
    asm("mov.b64 %0, {%1, %1};" : "=l"(d) : "f"(x));
    return d;
}
__device__ __forceinline__ void unpack2(u64 v, float& lo, float& hi) {
    asm("mov.b64 {%0, %1}, %2;" : "=f"(lo), "=f"(hi) : "l"(v));
}

// ---------------------------------------------------------------------------
// Kernel A (unchanged from round 2): bias = relu((ctab+pos) @ W1 + b1) @ W2
// ---------------------------------------------------------------------------
__global__ __launch_bounds__(128) void mlp_kernel(
    const float* __restrict__ glob, const float* __restrict__ ctab,
    const float* __restrict__ W1,   const float* __restrict__ b1,
    const float* __restrict__ W2)
{
    __shared__ __align__(16) float4 w1s[DHID];
    __shared__ __align__(16) float  w2s[DHID * HEADS];

    const int tid = threadIdx.x;
    {
        const float4* src = (const float4*)W2;
        float4* dst = (float4*)w2s;
        #pragma unroll
        for (int k = tid; k < DHID * HEADS / 4; k += 128) dst[k] = src[k];
        for (int d = tid; d < DHID; d += 128)
            w1s[d] = make_float4(W1[d], W1[DHID + d], b1[d], 0.0f);
    }
    __syncthreads();

    const int b = blockIdx.y;
    const float g0 = glob[b*4+0], g1 = glob[b*4+1];
    const float g2 = glob[b*4+2], g3 = glob[b*4+3];
    float p0 = g2 / g0 * 8.0f;
    float p1 = g3 / g1 * 8.0f;
    p0 = copysignf(log2f(fabsf(p0) + 1.0f), p0) * (2.0f / 3.0f) - 1.0f;
    p1 = copysignf(log2f(fabsf(p1) + 1.0f), p1) * (2.0f / 3.0f) - 1.0f;

    const int t0 = blockIdx.x * 256 + tid;
    const int t1 = t0 + 128;
    const bool v0 = (t0 < NT), v1 = (t1 < NT);

    float a0 = 0.f, a1 = 0.f, c0 = 0.f, c1 = 0.f;
    if (v0) { a0 = ctab[2*t0] + p0; a1 = ctab[2*t0+1] + p1; }
    if (v1) { c0 = ctab[2*t1] + p0; c1 = ctab[2*t1+1] + p1; }

    u64 accA[8], accB[8];
    #pragma unroll
    for (int k = 0; k < 8; k++) { accA[k] = 0ull; accB[k] = 0ull; }

    const ulonglong2* __restrict__ w2q = (const ulonglong2*)w2s;

    #pragma unroll 2
    for (int d = 0; d < DHID; d++) {
        const float4 w = w1s[d];
        float hA = fmaxf(fmaf(a0, w.x, fmaf(a1, w.y, w.z)), 0.0f);
        float hB = fmaxf(fmaf(c0, w.x, fmaf(c1, w.y, w.z)), 0.0f);
        const u64 hA2 = pack2(hA);
        const u64 hB2 = pack2(hB);
        const ulonglong2 q0 = w2q[d*4 + 0];
        const ulonglong2 q1 = w2q[d*4 + 1];
        const ulonglong2 q2 = w2q[d*4 + 2];
        const ulonglong2 q3 = w2q[d*4 + 3];
        accA[0] = fma2(hA2, q0.x, accA[0]);  accB[0] = fma2(hB2, q0.x, accB[0]);
        accA[1] = fma2(hA2, q0.y, accA[1]);  accB[1] = fma2(hB2, q0.y, accB[1]);
        accA[2] = fma2(hA2, q1.x, accA[2]);  accB[2] = fma2(hB2, q1.x, accB[2]);
        accA[3] = fma2(hA2, q1.y, accA[3]);  accB[3] = fma2(hB2, q1.y, accB[3]);
        accA[4] = fma2(hA2, q2.x, accA[4]);  accB[4] = fma2(hB2, q2.x, accB[4]);
        accA[5] = fma2(hA2, q2.y, accA[5]);  accB[5] = fma2(hB2, q2.y, accB[5]);
        accA[6] = fma2(hA2, q3.x, accA[6]);  accB[6] = fma2(hB2, q3.x, accB[6]);
        accA[7] = fma2(hA2, q3.y, accA[7]);  accB[7] = fma2(hB2, q3.y, accB[7]);
    }

    float* base = g_bias + (size_t)b * (HEADS * NT);
    if (v0) {
        #pragma unroll
        for (int k = 0; k < 8; k++) {
            float lo, hi; unpack2(accA[k], lo, hi);
            base[(2*k)   * NT + t0] = lo;
            base[(2*k+1) * NT + t0] = hi;
        }
    }
    if (v1) {
        #pragma unroll
        for (int k = 0; k < 8; k++) {
            float lo, hi; unpack2(accB[k], lo, hi);
            base[(2*k)   * NT + t1] = lo;
            base[(2*k+1) * NT + t1] = hi;
        }
    }
}

// ---------------------------------------------------------------------------
// Kernel B — diagonal-window scatter.
//   val(r=1+24ib+ii, c>=1) = rev[(23-ii) + f(c)],  f(c)=(c-1)+23*((c-1)/24)
//   rev[x] = bias_slice[1127-x]; values constant along (ii+1,c+1) diagonals.
// Block = (ib, plane). 6 warps; warp w owns 4 rows ii = 4w..4w+3.
// Lane handles a 4x4 tile: aligned float4 store per row (row di quad shifted
// by -di to keep 16B alignment as 577 = 1 mod 4). All 16 values come from
// two 10-word register windows of rev (base A-6, and A-29/A+17 for run
// crossings) selected by static indices.
// ---------------------------------------------------------------------------
#define FRONT 32

__global__ __launch_bounds__(192) void scatter_kernel(float* __restrict__ out)
{
    __shared__ float sh[1536];
    const int tid   = threadIdx.x;
    const int ib    = blockIdx.x;     // 0..23 bands, 24 = zero-row writer
    const int plane = blockIdx.y;     // 0..511
    float* __restrict__ pb = out + (size_t)plane * PLANE;

    if (ib == 24) {                   // row 0 is all zeros
        for (int c = tid; c < OW; c += 192) pb[c] = 0.0f;
        return;
    }

    // stage reversed + padded (phys = a + a>>2, conflict-free for stride-4 lanes)
    const float* __restrict__ bp = g_bias + (size_t)plane * NT + 47 * ib;
    for (int u = tid; u < 1128; u += 192) {
        int a = (1127 - u) + FRONT;
        sh[a + (a >> 2)] = bp[u];
    }
    __syncthreads();

    const int w    = tid >> 5;
    const int lane = tid & 31;
    const int ii0  = 4 * w;
    const int r0   = 1 + 24 * ib + ii0;
    const int basev = 23 - ii0;
    const int alpha = (int)(((size_t)plane * PLANE + (size_t)r0 * OW) & 3);
    const int cs    = (4 - alpha) & 3;          // first aligned col for row di=0
    float* __restrict__ rp = pb + (size_t)r0 * OW;

    for (int t = 0; t < 5; t++) {
        const int k = lane + 32 * t;
        if (k > 144) continue;
        const int cbase = cs + 4 * k;

        if (cbase >= 4 && cbase <= 573) {
            // ---- interior fast path: 4 rows x 4 cols from register windows
            const int j0 = cbase - 1;
            const int q0 = (j0 * 2731) >> 16;       // j0 / 24
            const int m0 = j0 - 24 * q0;
            const int A  = basev + j0 + 23 * q0 + FRONT;

            float wv[10], wc[10];
            {
                const int aW = A - 6;
                #pragma unroll
                for (int i = 0; i < 10; i++) { int a = aW + i; wv[i] = sh[a + (a >> 2)]; }
                const int aC = (m0 <= 2) ? (A - 29) : (A + 17);
                #pragma unroll
                for (int i = 0; i < 10; i++) { int a = aC + i; wc[i] = sh[a + (a >> 2)]; }
            }

            #pragma unroll
            for (int di = 0; di < 4; di++) {
                float4 v;
                float* vv = (float*)&v;
                #pragma unroll
                for (int e = 0; e < 4; e++) {
                    const int x   = e - di;          // static
                    const int idx = e - 2 * di + 6;  // static, in [0,9]
                    bool cross;
                    if      (x > 0) cross = (m0 >= 24 - x);  // fwd run crossing
                    else if (x < 0) cross = (m0 <  -x);      // bwd run crossing
                    else            cross = false;
                    vv[e] = cross ? wc[idx] : wv[idx];
                }
                *(float4*)(rp + di * OW + (cbase - di)) = v;
            }
        } else {
            // ---- edge path: scalar, covers head [0, cbase-di+3] and tail clip
            #pragma unroll
            for (int di = 0; di < 4; di++) {
                int clo = (k == 0) ? 0 : (cbase - di);
                int chi = cbase - di + 3;
                if (chi > 576) chi = 576;
                for (int c = clo; c <= chi; c++) {
                    float val = 0.0f;
                    if (c >= 1) {
                        const int j = c - 1;
                        const int q = (j * 2731) >> 16;
                        const int a = basev - di + j + 23 * q + FRONT;
                        val = sh[a + (a >> 2)];
                    }
                    rp[di * OW + c] = val;
                }
            }
        }
    }
}

// ---------------------------------------------------------------------------
extern "C" void kernel_launch(void* const* d_in, const int* in_sizes, int n_in,
                              void* d_out, int out_size)
{
    const float* glob = (const float*)d_in[0];
    const float* ctab = (const float*)d_in[1];
    const float* W1   = (const float*)d_in[3];
    const float* b1   = (const float*)d_in[4];
    const float* W2   = (const float*)d_in[5];
    float* out        = (float*)d_out;

    mlp_kernel<<<dim3((NT + 255) / 256, BATCH), 128>>>(glob, ctab, W1, b1, W2);
    scatter_kernel<<<dim3(25, BATCH * HEADS), 192>>>(out);
}